// round 1
// baseline (speedup 1.0000x reference)
#include <cuda_runtime.h>

// ---------------------------------------------------------------------------
// Problem constants
// ---------------------------------------------------------------------------
#define TOK   8192      // B*S tokens
#define DIMN  512       // ATTN_DIM
#define SEQ   512
#define NBAT  16
#define NHEAD 8
#define DHEAD 64
#define FFD   2048
#define CBSZ  8192
#define CBD   64

// ---------------------------------------------------------------------------
// Device scratch (static globals: allocation is forbidden)
// ---------------------------------------------------------------------------
__device__ float g_h  [TOK * DIMN];
__device__ float g_lnb[TOK * DIMN];
__device__ float g_qb [TOK * DIMN];
__device__ float g_kb [TOK * DIMN];
__device__ float g_vb [TOK * DIMN];
__device__ float g_att[TOK * DIMN];
__device__ float g_ffb[TOK * FFD];
__device__ float g_sc [(size_t)NBAT * NHEAD * SEQ * SEQ];   // 128 MB
__device__ float g_z  [TOK * CBD];
__device__ float g_cn [CBSZ];
__device__ int   g_idx[TOK];
__device__ float g_part[NBAT];

// ---------------------------------------------------------------------------
// Helpers
// ---------------------------------------------------------------------------
enum { EPI_NONE = 0, EPI_BIAS = 1, EPI_BIAS_POS = 2, EPI_RES = 3,
       EPI_RES_BIAS = 4, EPI_GELU_BIAS = 5 };

__device__ __forceinline__ float gelu_f(float x) {
    // jax.nn.gelu default (approximate=True, tanh form)
    float x3 = x * x * x;
    float t  = tanhf(0.7978845608028654f * (x + 0.044715f * x3));
    return 0.5f * x * (1.0f + t);
}

__device__ __forceinline__ unsigned long long dup2(float a) {
    unsigned long long r;
    asm("mov.b64 %0, {%1, %1};" : "=l"(r) : "f"(a));
    return r;
}
__device__ __forceinline__ void fma2(unsigned long long& d,
                                     unsigned long long a,
                                     unsigned long long b) {
    asm("fma.rn.f32x2 %0, %1, %2, %0;" : "+l"(d) : "l"(a), "l"(b));
}
__device__ __forceinline__ float2 unpack2(unsigned long long v) {
    float2 r;
    asm("mov.b64 {%0, %1}, %2;" : "=f"(r.x), "=f"(r.y) : "l"(v));
    return r;
}

// ---------------------------------------------------------------------------
// SGEMM: C[M,N] = A[M,K] @ B[K,N] (+epilogue). M multiple of 128 (always 8192).
// 128x128 block, BK=16, 8x8 microtile, f32x2 packed FMAs (2x fp32 rate).
// ---------------------------------------------------------------------------
__global__ __launch_bounds__(256)
void sgemm_k(const float* __restrict__ A, const float* __restrict__ B,
             float* __restrict__ C, const float* __restrict__ bias,
             const float* __restrict__ extra, int N, int K, int epi)
{
    __shared__ float As[16][128];
    __shared__ float Bs[16][128];
    const int tid  = threadIdx.x;
    const int row0 = blockIdx.y * 128;
    const int col0 = blockIdx.x * 128;
    const int trow = tid >> 4;
    const int tcol = tid & 15;

    unsigned long long acc[8][4];
#pragma unroll
    for (int i = 0; i < 8; i++)
#pragma unroll
        for (int j = 0; j < 4; j++) acc[i][j] = 0ULL;

    for (int k0 = 0; k0 < K; k0 += 16) {
#pragma unroll
        for (int v = 0; v < 2; v++) {
            int idx = tid + v * 256;
            // A tile: 128 rows x 16 k -> 512 float4, transpose-store
            int r  = idx >> 2;
            int kq = (idx & 3) << 2;
            float4 t = *(const float4*)(A + (long long)(row0 + r) * K + (k0 + kq));
            As[kq + 0][r] = t.x; As[kq + 1][r] = t.y;
            As[kq + 2][r] = t.z; As[kq + 3][r] = t.w;
            // B tile: 16 k x 128 cols
            int rb = idx >> 5;
            int cb = (idx & 31) << 2;
            float4 u = make_float4(0.f, 0.f, 0.f, 0.f);
            if (col0 + cb < N)
                u = *(const float4*)(B + (long long)(k0 + rb) * N + (col0 + cb));
            *(float4*)(&Bs[rb][cb]) = u;
        }
        __syncthreads();
#pragma unroll
        for (int kk = 0; kk < 16; kk++) {
            unsigned long long a2[8], b2[4];
            const float* ap = &As[kk][trow * 8];
            const unsigned long long* bp =
                (const unsigned long long*)(&Bs[kk][tcol * 8]);
#pragma unroll
            for (int j = 0; j < 4; j++) b2[j] = bp[j];
#pragma unroll
            for (int i = 0; i < 8; i++) a2[i] = dup2(ap[i]);
#pragma unroll
            for (int i = 0; i < 8; i++)
#pragma unroll
                for (int j = 0; j < 4; j++) fma2(acc[i][j], a2[i], b2[j]);
        }
        __syncthreads();
    }

#pragma unroll
    for (int i = 0; i < 8; i++) {
        int r = row0 + trow * 8 + i;
#pragma unroll
        for (int j = 0; j < 4; j++) {
            int c = col0 + tcol * 8 + j * 2;
            if (c >= N) continue;
            float2 v = unpack2(acc[i][j]);
            if (epi == EPI_BIAS || epi == EPI_RES_BIAS ||
                epi == EPI_GELU_BIAS || epi == EPI_BIAS_POS) {
                v.x += bias[c]; v.y += bias[c + 1];
            }
            if (epi == EPI_BIAS_POS) {
                const float* p = extra + (long long)(r & (SEQ - 1)) * N;
                v.x += p[c]; v.y += p[c + 1];
            }
            if (epi == EPI_RES || epi == EPI_RES_BIAS) {
                const float* p = extra + (long long)r * N;
                v.x += p[c]; v.y += p[c + 1];
            }
            if (epi == EPI_GELU_BIAS) { v.x = gelu_f(v.x); v.y = gelu_f(v.y); }
            *(float2*)(C + (long long)r * N + c) = v;
        }
    }
}

// ---------------------------------------------------------------------------
// LayerNorm (row = 512)
// ---------------------------------------------------------------------------
__global__ void layernorm_k(const float* __restrict__ X, float* __restrict__ Y,
                            const float* __restrict__ gg, const float* __restrict__ bb)
{
    __shared__ float sm[16];
    const int row = blockIdx.x;
    const int t   = threadIdx.x;
    const float* x = X + (long long)row * DIMN;
    float v0 = x[t], v1 = x[t + 256];
    float s = v0 + v1;
    float q = v0 * v0 + v1 * v1;
#pragma unroll
    for (int off = 16; off; off >>= 1) {
        s += __shfl_xor_sync(0xffffffffu, s, off);
        q += __shfl_xor_sync(0xffffffffu, q, off);
    }
    if ((t & 31) == 0) { sm[t >> 5] = s; sm[8 + (t >> 5)] = q; }
    __syncthreads();
    float S = 0.f, Q = 0.f;
#pragma unroll
    for (int i = 0; i < 8; i++) { S += sm[i]; Q += sm[8 + i]; }
    float mu  = S * (1.0f / DIMN);
    float var = Q * (1.0f / DIMN) - mu * mu;
    float inv = 1.0f / sqrtf(var + 1e-5f);
    Y[(long long)row * DIMN + t]       = (v0 - mu) * inv * gg[t]       + bb[t];
    Y[(long long)row * DIMN + t + 256] = (v1 - mu) * inv * gg[t + 256] + bb[t + 256];
}

// ---------------------------------------------------------------------------
// Attention: scores = Q K^T * DH^-0.5  (64x64 tile per block)
// grid (8 qtiles, 8 ktiles, 128 bh)
// ---------------------------------------------------------------------------
__global__ __launch_bounds__(256)
void attn_scores_k(const float* __restrict__ Q, const float* __restrict__ Kv,
                   float* __restrict__ S)
{
    const int qt = blockIdx.x, kt = blockIdx.y, bh = blockIdx.z;
    const int b = bh >> 3, h = bh & 7;
    __shared__ float Qs[64][65];
    __shared__ float Ks[64][65];
    const int tid = threadIdx.x;
#pragma unroll
    for (int v = 0; v < 4; v++) {
        int idx = tid + v * 256;
        int r = idx >> 4, c = (idx & 15) << 2;
        float4 tq = *(const float4*)(Q  + (long long)(b * SEQ + qt * 64 + r) * DIMN + h * 64 + c);
        Qs[r][c] = tq.x; Qs[r][c + 1] = tq.y; Qs[r][c + 2] = tq.z; Qs[r][c + 3] = tq.w;
        float4 tk = *(const float4*)(Kv + (long long)(b * SEQ + kt * 64 + r) * DIMN + h * 64 + c);
        Ks[r][c] = tk.x; Ks[r][c + 1] = tk.y; Ks[r][c + 2] = tk.z; Ks[r][c + 3] = tk.w;
    }
    __syncthreads();
    const int ty = tid >> 4, tx = tid & 15;
    float acc[4][4] = {};
#pragma unroll 8
    for (int d = 0; d < 64; d++) {
        float qv[4], kv[4];
#pragma unroll
        for (int i = 0; i < 4; i++) qv[i] = Qs[ty * 4 + i][d];
#pragma unroll
        for (int j = 0; j < 4; j++) kv[j] = Ks[tx * 4 + j][d];
#pragma unroll
        for (int i = 0; i < 4; i++)
#pragma unroll
            for (int j = 0; j < 4; j++) acc[i][j] += qv[i] * kv[j];
    }
#pragma unroll
    for (int i = 0; i < 4; i++) {
        int qrow = qt * 64 + ty * 4 + i;
        float4 o = make_float4(acc[i][0] * 0.125f, acc[i][1] * 0.125f,
                               acc[i][2] * 0.125f, acc[i][3] * 0.125f);
        *(float4*)(S + ((size_t)bh * SEQ + qrow) * SEQ + kt * 64 + tx * 4) = o;
    }
}

// ---------------------------------------------------------------------------
// Row softmax over 512 (one block per row)
// ---------------------------------------------------------------------------
__global__ void softmax_k(float* __restrict__ S)
{
    __shared__ float sm[8];
    const size_t row = blockIdx.x;
    float* p = S + row * SEQ;
    const int t = threadIdx.x;
    float v0 = p[t], v1 = p[t + 256];
    float m = fmaxf(v0, v1);
#pragma unroll
    for (int off = 16; off; off >>= 1) m = fmaxf(m, __shfl_xor_sync(0xffffffffu, m, off));
    if ((t & 31) == 0) sm[t >> 5] = m;
    __syncthreads();
    float M = sm[0];
#pragma unroll
    for (int i = 1; i < 8; i++) M = fmaxf(M, sm[i]);
    __syncthreads();
    float e0 = __expf(v0 - M), e1 = __expf(v1 - M);
    float s = e0 + e1;
#pragma unroll
    for (int off = 16; off; off >>= 1) s += __shfl_xor_sync(0xffffffffu, s, off);
    if ((t & 31) == 0) sm[t >> 5] = s;
    __syncthreads();
    float T = 0.f;
#pragma unroll
    for (int i = 0; i < 8; i++) T += sm[i];
    float inv = 1.0f / T;
    p[t] = e0 * inv;
    p[t + 256] = e1 * inv;
}

// ---------------------------------------------------------------------------
// O = A @ V per (bh, qtile): 64q x 64d, K=512
// ---------------------------------------------------------------------------
__global__ __launch_bounds__(256)
void attn_av_k(const float* __restrict__ S, const float* __restrict__ V,
               float* __restrict__ O)
{
    const int qt = blockIdx.x, bh = blockIdx.y;
    const int b = bh >> 3, h = bh & 7;
    __shared__ float As[64][65];
    __shared__ float Vs[64][65];
    const int tid = threadIdx.x;
    const int ty = tid >> 4, tx = tid & 15;
    float acc[4][4] = {};
    for (int k0 = 0; k0 < SEQ; k0 += 64) {
#pragma unroll
        for (int v = 0; v < 4; v++) {
            int idx = tid + v * 256;
            int r = idx >> 4, c = (idx & 15) << 2;
            float4 ta = *(const float4*)(S + ((size_t)bh * SEQ + qt * 64 + r) * SEQ + k0 + c);
            As[r][c] = ta.x; As[r][c + 1] = ta.y; As[r][c + 2] = ta.z; As[r][c + 3] = ta.w;
            float4 tv = *(const float4*)(V + (long long)(b * SEQ + k0 + r) * DIMN + h * 64 + c);
            Vs[r][c] = tv.x; Vs[r][c + 1] = tv.y; Vs[r][c + 2] = tv.z; Vs[r][c + 3] = tv.w;
        }
        __syncthreads();
#pragma unroll 8
        for (int kk = 0; kk < 64; kk++) {
            float a[4], vv[4];
#pragma unroll
            for (int i = 0; i < 4; i++) a[i] = As[ty * 4 + i][kk];
#pragma unroll
            for (int j = 0; j < 4; j++) vv[j] = Vs[kk][tx * 4 + j];
#pragma unroll
            for (int i = 0; i < 4; i++)
#pragma unroll
                for (int j = 0; j < 4; j++) acc[i][j] += a[i] * vv[j];
        }
        __syncthreads();
    }
#pragma unroll
    for (int i = 0; i < 4; i++) {
        int row = b * SEQ + qt * 64 + ty * 4 + i;
        float4 o = make_float4(acc[i][0], acc[i][1], acc[i][2], acc[i][3]);
        *(float4*)(O + (long long)row * DIMN + h * 64 + tx * 4) = o;
    }
}

// ---------------------------------------------------------------------------
// VQ: cnorm, argmin, reduce
// ---------------------------------------------------------------------------
__global__ void cb_norm_k(const float* __restrict__ cb)
{
    int c = blockIdx.x * 256 + threadIdx.x;
    float s = 0.f;
    const float* p = cb + (long long)c * CBD;
#pragma unroll 8
    for (int d = 0; d < CBD; d++) { float v = p[d]; s += v * v; }
    g_cn[c] = 0.5f * s;
}

__global__ __launch_bounds__(256)
void vq_argmin_k(const float* __restrict__ Z, const float* __restrict__ cb)
{
    const int zb = blockIdx.x;          // 128 blocks * 64 rows
    __shared__ float Zs[64][65];
    __shared__ float Cs[64][65];
    const int tid = threadIdx.x;
    const int ty = tid >> 4, tx = tid & 15;
#pragma unroll
    for (int v = 0; v < 4; v++) {
        int idx = tid + v * 256;
        int r = idx >> 4, c = (idx & 15) << 2;
        float4 t = *(const float4*)(Z + (long long)(zb * 64 + r) * CBD + c);
        Zs[r][c] = t.x; Zs[r][c + 1] = t.y; Zs[r][c + 2] = t.z; Zs[r][c + 3] = t.w;
    }
    __syncthreads();

    float bestv[4]; int bestc[4];
#pragma unroll
    for (int i = 0; i < 4; i++) { bestv[i] = -1e30f; bestc[i] = 0; }

    for (int c0 = 0; c0 < CBSZ; c0 += 64) {
#pragma unroll
        for (int v = 0; v < 4; v++) {
            int idx = tid + v * 256;
            int r = idx >> 4, c = (idx & 15) << 2;
            float4 t = *(const float4*)(cb + (long long)(c0 + r) * CBD + c);
            Cs[r][c] = t.x; Cs[r][c + 1] = t.y; Cs[r][c + 2] = t.z; Cs[r][c + 3] = t.w;
        }
        __syncthreads();
        float acc[4][4] = {};
#pragma unroll 8
        for (int d = 0; d < 64; d++) {
            float zv[4], cv[4];
#pragma unroll
            for (int i = 0; i < 4; i++) zv[i] = Zs[ty * 4 + i][d];
#pragma unroll
            for (int j = 0; j < 4; j++) cv[j] = Cs[tx * 4 + j][d];
#pragma unroll
            for (int i = 0; i < 4; i++)
#pragma unroll
                for (int j = 0; j < 4; j++) acc[i][j] += zv[i] * cv[j];
        }
#pragma unroll
        for (int i = 0; i < 4; i++)
#pragma unroll
            for (int j = 0; j < 4; j++) {
                int c = c0 + tx * 4 + j;
                float scv = acc[i][j] - g_cn[c];
                if (scv > bestv[i]) { bestv[i] = scv; bestc[i] = c; }
            }
        __syncthreads();
    }
    // reduce across the 16 tx threads of each row (half-warp shuffle)
#pragma unroll
    for (int i = 0; i < 4; i++) {
        float v = bestv[i]; int c = bestc[i];
#pragma unroll
        for (int off = 8; off; off >>= 1) {
            float ov = __shfl_xor_sync(0xffffffffu, v, off);
            int   oc = __shfl_xor_sync(0xffffffffu, c, off);
            if (ov > v || (ov == v && oc < c)) { v = ov; c = oc; }
        }
        if (tx == 0) g_idx[zb * 64 + ty * 4 + i] = c;
    }
}

__global__ void vq_reduce_k(const float* __restrict__ cb,
                            const float* __restrict__ Z,
                            float* __restrict__ out)
{
    __shared__ float ssum[256];
    __shared__ float sloss[256];
    const int b = blockIdx.x;
    const int tid = threadIdx.x;
    const int d = tid & 63;
    const int sg = tid >> 6;
    float sum = 0.f, loss = 0.f;
    for (int s = sg; s < SEQ; s += 4) {
        int c = g_idx[b * SEQ + s];
        float qv = cb[(long long)c * CBD + d];
        float zv = Z[((long long)b * SEQ + s) * CBD + d];
        sum += qv;
        float dd = qv - zv;
        loss += dd * dd;
    }
    ssum[tid] = sum; sloss[tid] = loss;
    __syncthreads();
    if (tid < 64)
        out[b * CBD + tid] = ssum[tid] + ssum[tid + 64] + ssum[tid + 128] + ssum[tid + 192];
    for (int st = 128; st > 0; st >>= 1) {
        if (tid < st) sloss[tid] += sloss[tid + st];
        __syncthreads();
    }
    if (tid == 0) g_part[b] = sloss[0];
}

__global__ void vq_finish_k(float* __restrict__ out, int out_size)
{
    if (threadIdx.x == 0 && out_size > NBAT * CBD) {
        float s = 0.f;
        for (int i = 0; i < NBAT; i++) s += g_part[i];
        out[NBAT * CBD] = s / (float)(TOK * CBD);
    }
}

// ---------------------------------------------------------------------------
// Launch
// ---------------------------------------------------------------------------
extern "C" void kernel_launch(void* const* d_in, const int* in_sizes, int n_in,
                              void* d_out, int out_size)
{
    (void)in_sizes; (void)n_in;
    const float* x    = (const float*)d_in[0];
    const float* w_in = (const float*)d_in[1];
    const float* b_in = (const float*)d_in[2];
    const float* pos  = (const float*)d_in[3];
    const float* ln1g = (const float*)d_in[4];
    const float* ln1b = (const float*)d_in[5];
    const float* wq   = (const float*)d_in[6];
    const float* wk   = (const float*)d_in[7];
    const float* wv   = (const float*)d_in[8];
    const float* wo   = (const float*)d_in[9];
    const float* ln2g = (const float*)d_in[10];
    const float* ln2b = (const float*)d_in[11];
    const float* fw1  = (const float*)d_in[12];
    const float* fb1  = (const float*)d_in[13];
    const float* fw2  = (const float*)d_in[14];
    const float* fb2  = (const float*)d_in[15];
    const float* lnfg = (const float*)d_in[16];
    const float* lnfb = (const float*)d_in[17];
    const float* wout = (const float*)d_in[18];
    const float* bout = (const float*)d_in[19];
    const float* cbk  = (const float*)d_in[20];
    float* out = (float*)d_out;

    float *h, *ln, *qb, *kb, *vb, *att, *ff, *sc, *z;
    cudaGetSymbolAddress((void**)&h,   g_h);
    cudaGetSymbolAddress((void**)&ln,  g_lnb);
    cudaGetSymbolAddress((void**)&qb,  g_qb);
    cudaGetSymbolAddress((void**)&kb,  g_kb);
    cudaGetSymbolAddress((void**)&vb,  g_vb);
    cudaGetSymbolAddress((void**)&att, g_att);
    cudaGetSymbolAddress((void**)&ff,  g_ffb);
    cudaGetSymbolAddress((void**)&sc,  g_sc);
    cudaGetSymbolAddress((void**)&z,   g_z);

    const dim3 g512(4, 64), g2048(16, 64), g64(1, 64);

    // input projection + pos emb
    sgemm_k<<<g512, 256>>>(x, w_in, h, b_in, pos, DIMN, DIMN, EPI_BIAS_POS);

    for (int l = 0; l < 4; l++) {
        layernorm_k<<<TOK, 256>>>(h, ln, ln1g + l * DIMN, ln1b + l * DIMN);
        sgemm_k<<<g512, 256>>>(ln, wq + (long long)l * DIMN * DIMN, qb, nullptr, nullptr, DIMN, DIMN, EPI_NONE);
        sgemm_k<<<g512, 256>>>(ln, wk + (long long)l * DIMN * DIMN, kb, nullptr, nullptr, DIMN, DIMN, EPI_NONE);
        sgemm_k<<<g512, 256>>>(ln, wv + (long long)l * DIMN * DIMN, vb, nullptr, nullptr, DIMN, DIMN, EPI_NONE);
        attn_scores_k<<<dim3(8, 8, NBAT * NHEAD), 256>>>(qb, kb, sc);
        softmax_k<<<NBAT * NHEAD * SEQ, 256>>>(sc);
        attn_av_k<<<dim3(8, NBAT * NHEAD), 256>>>(sc, vb, att);
        sgemm_k<<<g512, 256>>>(att, wo + (long long)l * DIMN * DIMN, h, nullptr, h, DIMN, DIMN, EPI_RES);
        layernorm_k<<<TOK, 256>>>(h, ln, ln2g + l * DIMN, ln2b + l * DIMN);
        sgemm_k<<<g2048, 256>>>(ln, fw1 + (long long)l * DIMN * FFD, ff, fb1 + l * FFD, nullptr, FFD, DIMN, EPI_GELU_BIAS);
        sgemm_k<<<g512, 256>>>(ff, fw2 + (long long)l * FFD * DIMN, h, fb2 + l * DIMN, h, DIMN, FFD, EPI_RES_BIAS);
    }

    layernorm_k<<<TOK, 256>>>(h, ln, lnfg, lnfb);
    sgemm_k<<<g64, 256>>>(ln, wout, z, bout, nullptr, CBD, DIMN, EPI_BIAS);

    cb_norm_k<<<CBSZ / 256, 256>>>(cbk);
    vq_argmin_k<<<TOK / 64, 256>>>(z, cbk);
    vq_reduce_k<<<NBAT, 256>>>(cbk, z, out);
    vq_finish_k<<<1, 32>>>(out, out_size);
}